// round 5
// baseline (speedup 1.0000x reference)
#include <cuda_runtime.h>
#include <math.h>

#define B_ 2
#define L_ 2048
#define H_ 8
#define E_ 64
#define D_ 64
#define SSTR 68           // smem row stride for K/V (floats)
#define DSTR 132          // smem row stride for duplicated arrays (floats)
#define NTILE 32          // L_/64

typedef unsigned long long ull;

__device__ float g_sig[B_*H_*L_];
__device__ float g_coef[B_*H_*L_];
__device__ float g_i2s2[B_*H_*L_];
__device__ float g_rl[B_*H_*L_];

__global__ void sigma_prep(const float* __restrict__ sigma) {
    int t = blockIdx.x * blockDim.x + threadIdx.x;
    if (t >= B_*H_*L_) return;
    int l  = t & (L_-1);
    int bh = t >> 11;
    int h  = bh & (H_-1);
    int b  = bh >> 3;
    float x  = sigma[((size_t)b*L_ + l)*H_ + h];
    float sgm = 1.f/(1.f + expf(-5.f*x));
    float sg  = sgm + 1e-5f;
    float p = powf(3.0f, sg);               // match XLA:GPU libdevice powf
    float s = p - 1.0f;
    g_sig[t]  = s;
    g_coef[t] = 0.3989422804014327f / s;
    g_i2s2[t] = 0.5f/(s*s);
}

__device__ __forceinline__ void fma2(ull& d, ull a, ull b) {
    asm("fma.rn.f32x2 %0, %1, %2, %0;" : "+l"(d) : "l"(a), "l"(b));
}
__device__ __forceinline__ float2 unpack2(ull d) {
    unsigned lo, hi;
    asm("mov.b64 {%0, %1}, %2;" : "=r"(lo), "=r"(hi) : "l"(d));
    return make_float2(__uint_as_float(lo), __uint_as_float(hi));
}

// ============ fused attention + prior + sigma_out + upper zeros ============
__global__ __launch_bounds__(256, 2)
void attn_main(const float* __restrict__ Q, const float* __restrict__ K,
               const float* __restrict__ V, float* __restrict__ out)
{
    extern __shared__ float sm[];
    float* Qd = sm;                   // [64][DSTR]  Q*scale, duplicated pairs
    float* Ks = sm + 64*DSTR;         // [64][SSTR]  K transposed (e-major)
    float* Vs = Ks + 64*SSTR;         // [64][SSTR]  V row-major
    float* Pd = Vs + 64*SSTR;         // [64][DSTR]  exp(S), duplicated pairs

    const int x  = blockIdx.x;
    const int h  = blockIdx.y;
    const int b  = blockIdx.z;
    const int tx = threadIdx.x;
    const int cg = tx & 15;
    const int rg = tx >> 4;
    const int rbase = rg * 4;
    const int bh = b*H_ + h;

    float* outV = out;
    float* outS = out + (size_t)B_*L_*H_*D_;
    float* outP = outS + (size_t)B_*H_*L_*L_;
    float* outG = outP + (size_t)B_*H_*L_*L_;

    const int kj = tx & 63;
    const int ke = tx >> 6;

    #pragma unroll 1
    for (int half = 0; half < 2; half++) {
        const int it = half ? (NTILE-1 - x) : x;
        const int i0 = it * 64;

        float sigk[4], coefk[4], i2s2k[4];
        #pragma unroll
        for (int k = 0; k < 4; k++) {
            int gi = bh*L_ + i0 + rbase + k;
            sigk[k] = g_sig[gi]; coefk[k] = g_coef[gi]; i2s2k[k] = g_i2s2[gi];
        }

        __syncthreads();
        // load Q tile scaled, store duplicated: Qd[row][2e]=Qd[row][2e+1]=q*0.125
        {
            const float* qp = Q + ((size_t)(b*L_ + i0)*H_ + h)*E_;
            int r = tx >> 4, ec = tx & 15;
            #pragma unroll
            for (int rr = 0; rr < 4; rr++) {
                int row = r + rr*16;
                float4 t4 = *(const float4*)(qp + (size_t)row*(H_*E_) + ec*4);
                float* dst = Qd + row*DSTR + ec*8;
                float4 d0 = make_float4(t4.x*0.125f, t4.x*0.125f, t4.y*0.125f, t4.y*0.125f);
                float4 d1 = make_float4(t4.z*0.125f, t4.z*0.125f, t4.w*0.125f, t4.w*0.125f);
                *(float4*)(dst)   = d0;
                *(float4*)(dst+4) = d1;
            }
        }

        float l[4] = {0.f,0.f,0.f,0.f};
        ull o2[4][2] = {};

        #pragma unroll 1
        for (int jt = 0; jt <= it; jt++) {
            const int j0 = jt*64;
            __syncthreads();
            const float* kp = K + ((size_t)(b*L_ + j0)*H_ + h)*E_;
            #pragma unroll
            for (int i = 0; i < 4; i++) {
                int ec = ke + i*4;
                float4 t4 = *(const float4*)(kp + (size_t)kj*(H_*E_) + ec*4);
                Ks[(ec*4+0)*SSTR + kj] = t4.x;
                Ks[(ec*4+1)*SSTR + kj] = t4.y;
                Ks[(ec*4+2)*SSTR + kj] = t4.z;
                Ks[(ec*4+3)*SSTR + kj] = t4.w;
            }
            {
                const float* vp = V + ((size_t)(b*L_ + j0)*H_ + h)*D_;
                int r = tx >> 4, ec = tx & 15;
                #pragma unroll
                for (int rr = 0; rr < 4; rr++) {
                    int row = r + rr*16;
                    *(float4*)(Vs + row*SSTR + ec*4) =
                        *(const float4*)(vp + (size_t)row*(H_*D_) + ec*4);
                }
            }
            __syncthreads();

            // ---- S = Q K^T : dup-Q packed operands, no movs ----
            ull s2[4][2] = {};
            #pragma unroll
            for (int e4 = 0; e4 < 16; e4++) {
                ull kc2[4][2];
                #pragma unroll
                for (int j = 0; j < 4; j++) {
                    const float4 kv = *(const float4*)(Ks + (e4*4+j)*SSTR + cg*4);
                    kc2[j][0] = *(const ull*)&kv.x;
                    kc2[j][1] = *(const ull*)&kv.z;
                }
                #pragma unroll
                for (int k = 0; k < 4; k++) {
                    const float* qb = Qd + (rbase+k)*DSTR + e4*8;
                    const float4 qa = *(const float4*)(qb);
                    const float4 qc = *(const float4*)(qb+4);
                    ull q0 = *(const ull*)&qa.x, q1 = *(const ull*)&qa.z;
                    ull q2 = *(const ull*)&qc.x, q3 = *(const ull*)&qc.z;
                    fma2(s2[k][0], q0, kc2[0][0]); fma2(s2[k][1], q0, kc2[0][1]);
                    fma2(s2[k][0], q1, kc2[1][0]); fma2(s2[k][1], q1, kc2[1][1]);
                    fma2(s2[k][0], q2, kc2[2][0]); fma2(s2[k][1], q2, kc2[2][1]);
                    fma2(s2[k][0], q3, kc2[3][0]); fma2(s2[k][1], q3, kc2[3][1]);
                }
            }

            // P = exp(S); causal mask on diag tile; series + dup-P store
            #pragma unroll
            for (int k = 0; k < 4; k++) {
                float2 a = unpack2(s2[k][0]), c = unpack2(s2[k][1]);
                float4 p4;
                p4.x = __expf(a.x); p4.y = __expf(a.y);
                p4.z = __expf(c.x); p4.w = __expf(c.y);
                if (jt == it) {
                    int irow = rbase + k, jc = cg*4;
                    if (jc+0 > irow) p4.x = 0.f;
                    if (jc+1 > irow) p4.y = 0.f;
                    if (jc+2 > irow) p4.z = 0.f;
                    if (jc+3 > irow) p4.w = 0.f;
                }
                l[k] += p4.x + p4.y + p4.z + p4.w;
                *(float4*)(outS + ((size_t)bh*L_ + i0+rbase+k)*L_ + j0 + cg*4) = p4;
                float* pdst = Pd + (rbase+k)*DSTR + cg*8;
                *(float4*)(pdst)   = make_float4(p4.x, p4.x, p4.y, p4.y);
                *(float4*)(pdst+4) = make_float4(p4.z, p4.z, p4.w, p4.w);
            }
            __syncthreads();

            // ---- O += P * V : dup-P packed operands ----
            #pragma unroll
            for (int j4 = 0; j4 < 16; j4++) {
                ull vr2[4][2];
                #pragma unroll
                for (int j = 0; j < 4; j++) {
                    const float4 vv = *(const float4*)(Vs + (j4*4+j)*SSTR + cg*4);
                    vr2[j][0] = *(const ull*)&vv.x;
                    vr2[j][1] = *(const ull*)&vv.z;
                }
                #pragma unroll
                for (int k = 0; k < 4; k++) {
                    const float* pb = Pd + (rbase+k)*DSTR + j4*8;
                    const float4 pa = *(const float4*)(pb);
                    const float4 pc = *(const float4*)(pb+4);
                    ull p0 = *(const ull*)&pa.x, p1 = *(const ull*)&pa.z;
                    ull p2 = *(const ull*)&pc.x, p3 = *(const ull*)&pc.z;
                    fma2(o2[k][0], p0, vr2[0][0]); fma2(o2[k][1], p0, vr2[0][1]);
                    fma2(o2[k][0], p1, vr2[1][0]); fma2(o2[k][1], p1, vr2[1][1]);
                    fma2(o2[k][0], p2, vr2[2][0]); fma2(o2[k][1], p2, vr2[2][1]);
                    fma2(o2[k][0], p3, vr2[3][0]); fma2(o2[k][1], p3, vr2[3][1]);
                }
            }

            // ---- prior + sigma for this tile ----
            #pragma unroll
            for (int k = 0; k < 4; k++) {
                const int irow = i0 + rbase + k;
                float vals[4];
                #pragma unroll
                for (int c = 0; c < 4; c++) {
                    int d = irow - (j0 + cg*4 + c);
                    float arg = -(float)(d*d) * i2s2k[k];
                    vals[c] = (arg > -87.f) ? (coefk[k] * __expf(arg)) : 0.f;
                }
                size_t off = ((size_t)bh*L_ + irow)*L_ + j0 + cg*4;
                *(float4*)(outP + off) = make_float4(vals[0],vals[1],vals[2],vals[3]);
                *(float4*)(outG + off) = make_float4(sigk[k],sigk[k],sigk[k],sigk[k]);
            }
        }

        // ---- non-causal tiles: zero series, prior, sigma ----
        #pragma unroll 1
        for (int jt = it+1; jt < NTILE; jt++) {
            const int j0 = jt*64;
            float4 z = make_float4(0.f,0.f,0.f,0.f);
            #pragma unroll
            for (int k = 0; k < 4; k++) {
                const int irow = i0 + rbase + k;
                float vals[4];
                #pragma unroll
                for (int c = 0; c < 4; c++) {
                    int d = irow - (j0 + cg*4 + c);
                    float arg = -(float)(d*d) * i2s2k[k];
                    vals[c] = (arg > -87.f) ? (coefk[k] * __expf(arg)) : 0.f;
                }
                size_t off = ((size_t)bh*L_ + irow)*L_ + j0 + cg*4;
                *(float4*)(outS + off) = z;
                *(float4*)(outP + off) = make_float4(vals[0],vals[1],vals[2],vals[3]);
                *(float4*)(outG + off) = make_float4(sigk[k],sigk[k],sigk[k],sigk[k]);
            }
        }

        #pragma unroll
        for (int k = 0; k < 4; k++) {
            #pragma unroll
            for (int o = 1; o < 16; o <<= 1) l[k] += __shfl_xor_sync(0xffffffffu, l[k], o);
        }
        float rl[4];
        #pragma unroll
        for (int k = 0; k < 4; k++) rl[k] = 1.f/l[k];
        if (cg == 0) {
            #pragma unroll
            for (int k = 0; k < 4; k++) g_rl[bh*L_ + i0+rbase+k] = rl[k];
        }
        #pragma unroll
        for (int k = 0; k < 4; k++) {
            float2 a = unpack2(o2[k][0]), c = unpack2(o2[k][1]);
            float4 o4 = make_float4(a.x*rl[k], a.y*rl[k], c.x*rl[k], c.y*rl[k]);
            *(float4*)(outV + (((size_t)(b*L_) + i0+rbase+k)*H_ + h)*D_ + cg*4) = o4;
        }
    }
}

// ============ slim epilogue: normalize lower-triangle series ============
__global__ __launch_bounds__(256)
void norm_series(float* __restrict__ out)
{
    const int i  = blockIdx.x;
    const int bh = blockIdx.y;
    const float rl = g_rl[bh*L_ + i];
    float* row = out + (size_t)B_*L_*H_*D_ + ((size_t)bh*L_ + i)*L_;
    const int ncols = (((i >> 6) + 1) << 6);
    for (int c = threadIdx.x*4; c < ncols; c += 256*4) {
        float4 s4 = *(const float4*)(row + c);
        s4.x *= rl; s4.y *= rl; s4.z *= rl; s4.w *= rl;
        *(float4*)(row + c) = s4;
    }
}

extern "C" void kernel_launch(void* const* d_in, const int* in_sizes, int n_in,
                              void* d_out, int out_size) {
    const float* q  = (const float*)d_in[0];
    const float* k  = (const float*)d_in[1];
    const float* v  = (const float*)d_in[2];
    const float* sg = (const float*)d_in[3];

    sigma_prep<<<(B_*H_*L_ + 255)/256, 256>>>(sg);

    const int smem_bytes = (2*64*DSTR + 2*64*SSTR)*(int)sizeof(float);  // 102400
    cudaFuncSetAttribute(attn_main, cudaFuncAttributeMaxDynamicSharedMemorySize, smem_bytes);
    dim3 grid(NTILE/2, H_, B_);
    attn_main<<<grid, 256, smem_bytes>>>(q, k, v, (float*)d_out);

    dim3 egrid(L_, B_*H_);
    norm_series<<<egrid, 256>>>((float*)d_out);
}

// round 7
// speedup vs baseline: 1.6156x; 1.6156x over previous
#include <cuda_runtime.h>
#include <cuda_bf16.h>
#include <cstdint>
#include <math.h>

#define B_ 2
#define L_ 2048
#define H_ 8
#define E_ 64
#define D_ 64
#define NTILE 32
#define PSTR 68

// ---------------- scratch ----------------
__device__ float g_sig[B_*H_*L_];
__device__ float g_coef[B_*H_*L_];
__device__ float g_i2s2[B_*H_*L_];
__device__ float g_rl[B_*H_*L_];

__global__ void sigma_prep(const float* __restrict__ sigma) {
    int t = blockIdx.x * blockDim.x + threadIdx.x;
    if (t >= B_*H_*L_) return;
    int l  = t & (L_-1);
    int bh = t >> 11;
    int h  = bh & (H_-1);
    int b  = bh >> 3;
    float x  = sigma[((size_t)b*L_ + l)*H_ + h];
    float sgm = 1.f/(1.f + expf(-5.f*x));
    float sg  = sgm + 1e-5f;
    float p = powf(3.0f, sg);               // match XLA:GPU libdevice powf
    float s = p - 1.0f;
    g_sig[t]  = s;
    g_coef[t] = 0.3989422804014327f / s;
    g_i2s2[t] = 0.5f/(s*s);
}

// ---------------- helpers ----------------
__device__ __forceinline__ uint32_t smem_u32(const void* p) {
    uint32_t a;
    asm("{ .reg .u64 t; cvta.to.shared.u64 t, %1; cvt.u32.u64 %0, t; }" : "=r"(a) : "l"(p));
    return a;
}
#define LDSM_X4(r, a) \
    asm volatile("ldmatrix.sync.aligned.m8n8.x4.shared.b16 {%0,%1,%2,%3}, [%4];" \
        : "=r"((r)[0]),"=r"((r)[1]),"=r"((r)[2]),"=r"((r)[3]) : "r"(a))
#define LDSM_X4T(r, a) \
    asm volatile("ldmatrix.sync.aligned.m8n8.x4.trans.shared.b16 {%0,%1,%2,%3}, [%4];" \
        : "=r"((r)[0]),"=r"((r)[1]),"=r"((r)[2]),"=r"((r)[3]) : "r"(a))
#define MMA_BF16(d, a, b0, b1) \
    asm volatile("mma.sync.aligned.m16n8k16.row.col.f32.bf16.bf16.f32 " \
        "{%0,%1,%2,%3}, {%4,%5,%6,%7}, {%8,%9}, {%0,%1,%2,%3};" \
        : "+f"((d)[0]),"+f"((d)[1]),"+f"((d)[2]),"+f"((d)[3]) \
        : "r"((a)[0]),"r"((a)[1]),"r"((a)[2]),"r"((a)[3]), "r"(b0),"r"(b1))

// swizzled smem address for 128B rows: 16B-unit c ^= (row&7)
__device__ __forceinline__ uint32_t swadr(uint32_t base, int row, int c16) {
    uint32_t off = (uint32_t)(row*128 + c16*16);
    return base + (off ^ ((off >> 3) & 0x70));
}
__device__ __forceinline__ uint32_t bf2x(float a, float b) {
    __nv_bfloat162 t = __floats2bfloat162_rn(a, b);
    return *(uint32_t*)&t;
}
__device__ __forceinline__ float bflo(float x) {  // x - bf16(x)
    return x - __bfloat162float(__float2bfloat16_rn(x));
}

// smem byte offsets (8KB per bf16 matrix: 64 rows x 128B)
#define SM_QHI 0
#define SM_QLO 8192
#define SM_KHI 16384
#define SM_KLO 24576
#define SM_VHI 32768
#define SM_VLO 40960
#define SM_PHI 49152
#define SM_PLO 57344
#define SM_PS  65536                      // fp32 [64][PSTR]
#define SM_RL  (SM_PS + 64*PSTR*4)        // fp32 [64]
#define SM_TOTAL (SM_RL + 256)

__global__ __launch_bounds__(256, 2)
void attn_tc(const float* __restrict__ Q, const float* __restrict__ K,
             const float* __restrict__ V, float* __restrict__ out)
{
    extern __shared__ char smc[];
    const uint32_t sb = smem_u32(smc);
    float* Ps = (float*)(smc + SM_PS);
    float* rlbuf = (float*)(smc + SM_RL);

    const int tx  = threadIdx.x;
    const int lid = tx & 31;
    const int wid = tx >> 5;
    const int wm  = wid & 3;            // m-band (16 rows)
    const int wn  = wid >> 2;           // n-band (32 cols)
    const int x = blockIdx.x, h = blockIdx.y, b = blockIdx.z;
    const int bh = b*H_ + h;

    float* outV = out;
    float* outS = out + (size_t)B_*L_*H_*D_;
    float* outP = outS + (size_t)B_*H_*L_*L_;
    float* outG = outP + (size_t)B_*H_*L_*L_;

    // per-lane ldmatrix row/col pieces
    const int a_row = wm*16 + (lid & 7) + ((lid >> 3) & 1)*8;   // A tiles (Q/P)
    const int a_c16 = (lid >> 4);                               // + kc*2
    const int bk_row = (lid & 7) + (lid >> 4)*8;                // B tiles (K), + n0
    const int bk_c16 = ((lid >> 3) & 1);                        // + kc*2
    const int bv_row = (lid & 7) + ((lid >> 3) & 1)*8;          // B tiles (V,trans), + kc*16
    const int bv_c16 = wn*4 + (lid >> 4);

    // gmem loader mapping (64x64 tile, 256 thr)
    const int grow = tx >> 2;
    const int gc0  = (tx & 3)*16;

    // store-loop mapping
    const int srow = tx >> 4;            // + p*16, p<4
    const int sc0  = (tx & 15)*4;

    #pragma unroll 1
    for (int hf = 0; hf < 2; hf++) {
        const int it = hf ? (NTILE-1 - x) : x;
        const int i0 = it * 64;
        const int jlim = it + 1;

        float coef4[4], i2s24[4], sig4[4];
        #pragma unroll
        for (int p = 0; p < 4; p++) {
            int gi = bh*L_ + i0 + srow + p*16;
            coef4[p] = g_coef[gi]; i2s24[p] = g_i2s2[gi]; sig4[p] = g_sig[gi];
        }

        __syncthreads();
        // ---- load + split Q (scaled 0.125) ----
        {
            const float* qp = Q + ((size_t)(b*L_ + i0)*H_ + h)*E_ + (size_t)grow*(H_*E_);
            #pragma unroll
            for (int g = 0; g < 4; g++) {
                int col = gc0 + g*4;
                float4 v = *(const float4*)(qp + col);
                v.x *= 0.125f; v.y *= 0.125f; v.z *= 0.125f; v.w *= 0.125f;
                uint32_t adr = swadr(sb, grow, (col*2) >> 4) + ((col*2) & 15);
                *(uint2*)(size_t)0; // placeholder removed below
                uint2 whi = make_uint2(bf2x(v.x, v.y), bf2x(v.z, v.w));
                uint2 wlo = make_uint2(bf2x(bflo(v.x), bflo(v.y)), bf2x(bflo(v.z), bflo(v.w)));
                *(uint2*)(smc + (adr - sb) + SM_QHI) = whi;
                *(uint2*)(smc + (adr - sb) + SM_QLO) = wlo;
            }
        }

        float lsum[4] = {0.f,0.f,0.f,0.f};
        float oacc[4][4] = {};

        #pragma unroll 1
        for (int jt = 0; jt < jlim; jt++) {
            const int j0 = jt*64;
            // ---- load + split K and V ----
            {
                const float* kp = K + ((size_t)(b*L_ + j0)*H_ + h)*E_ + (size_t)grow*(H_*E_);
                const float* vp = V + ((size_t)(b*L_ + j0)*H_ + h)*D_ + (size_t)grow*(H_*D_);
                #pragma unroll
                for (int g = 0; g < 4; g++) {
                    int col = gc0 + g*4;
                    uint32_t rel = (swadr(sb, grow, (col*2) >> 4) - sb) + ((col*2) & 15);
                    float4 v = *(const float4*)(kp + col);
                    *(uint2*)(smc + rel + SM_KHI) = make_uint2(bf2x(v.x, v.y), bf2x(v.z, v.w));
                    *(uint2*)(smc + rel + SM_KLO) = make_uint2(bf2x(bflo(v.x), bflo(v.y)), bf2x(bflo(v.z), bflo(v.w)));
                    v = *(const float4*)(vp + col);
                    *(uint2*)(smc + rel + SM_VHI) = make_uint2(bf2x(v.x, v.y), bf2x(v.z, v.w));
                    *(uint2*)(smc + rel + SM_VLO) = make_uint2(bf2x(bflo(v.x), bflo(v.y)), bf2x(bflo(v.z), bflo(v.w)));
                }
            }
            __syncthreads();

            // ---- S = Q K^T (3 split passes) ----
            float sacc[4][4] = {};
            #pragma unroll
            for (int kc = 0; kc < 4; kc++) {
                uint32_t ah[4], al[4], bh0[4], bh1[4], bl0[4], bl1[4];
                LDSM_X4(ah, swadr(sb + SM_QHI, a_row, a_c16 + kc*2));
                LDSM_X4(al, swadr(sb + SM_QLO, a_row, a_c16 + kc*2));
                LDSM_X4(bh0, swadr(sb + SM_KHI, wn*32 + bk_row,      bk_c16 + kc*2));
                LDSM_X4(bh1, swadr(sb + SM_KHI, wn*32 + 16 + bk_row, bk_c16 + kc*2));
                LDSM_X4(bl0, swadr(sb + SM_KLO, wn*32 + bk_row,      bk_c16 + kc*2));
                LDSM_X4(bl1, swadr(sb + SM_KLO, wn*32 + 16 + bk_row, bk_c16 + kc*2));
                #pragma unroll
                for (int nt = 0; nt < 4; nt++) {
                    const uint32_t* BH = (nt < 2) ? bh0 : bh1;
                    const uint32_t* BL = (nt < 2) ? bl0 : bl1;
                    int u = (nt & 1)*2;
                    MMA_BF16(sacc[nt], ah, BH[u], BH[u+1]);
                    MMA_BF16(sacc[nt], ah, BL[u], BL[u+1]);
                    MMA_BF16(sacc[nt], al, BH[u], BH[u+1]);
                }
            }

            // ---- exp + causal mask; stage Ps fp32 + split-P bf16 ----
            {
                const int r0 = wm*16 + (lid >> 2);
                const int r1 = r0 + 8;
                const int cb = wn*32 + (lid & 3)*2;
                #pragma unroll
                for (int nt = 0; nt < 4; nt++) {
                    int col = cb + nt*8;
                    float p0 = (j0+col   > i0+r0) ? 0.f : __expf(sacc[nt][0]);
                    float p1 = (j0+col+1 > i0+r0) ? 0.f : __expf(sacc[nt][1]);
                    float p2 = (j0+col   > i0+r1) ? 0.f : __expf(sacc[nt][2]);
                    float p3 = (j0+col+1 > i0+r1) ? 0.f : __expf(sacc[nt][3]);
                    *(float2*)(Ps + r0*PSTR + col) = make_float2(p0, p1);
                    *(float2*)(Ps + r1*PSTR + col) = make_float2(p2, p3);
                    uint32_t rel0 = (swadr(sb, r0, (col*2) >> 4) - sb) + ((col*2) & 15);
                    uint32_t rel1 = (swadr(sb, r1, (col*2) >> 4) - sb) + ((col*2) & 15);
                    *(uint32_t*)(smc + rel0 + SM_PHI) = bf2x(p0, p1);
                    *(uint32_t*)(smc + rel0 + SM_PLO) = bf2x(bflo(p0), bflo(p1));
                    *(uint32_t*)(smc + rel1 + SM_PHI) = bf2x(p2, p3);
                    *(uint32_t*)(smc + rel1 + SM_PLO) = bf2x(bflo(p2), bflo(p3));
                }
            }
            __syncthreads();

            // ---- O += P V (3 split passes) ----
            #pragma unroll
            for (int kc = 0; kc < 4; kc++) {
                uint32_t ah[4], al[4], bh2[4], bl2[4];
                LDSM_X4(ah, swadr(sb + SM_PHI, a_row, a_c16 + kc*2));
                LDSM_X4(al, swadr(sb + SM_PLO, a_row, a_c16 + kc*2));
                LDSM_X4T(bh2, swadr(sb + SM_VHI, kc*16 + bv_row, bv_c16));
                LDSM_X4T(bl2, swadr(sb + SM_VLO, kc*16 + bv_row, bv_c16));
                #pragma unroll
                for (int nt = 0; nt < 4; nt++) {
                    int u = (nt & 1)*2;
                    const uint32_t* BH = (nt < 2) ? bh2 : bh2 + 0;  // x4T covers 2 ntiles
                    const uint32_t* BL = (nt < 2) ? bl2 : bl2 + 0;
                    (void)BH; (void)BL;
                    if (nt < 2) {
                        MMA_BF16(oacc[nt], ah, bh2[u], bh2[u+1]);
                        MMA_BF16(oacc[nt], ah, bl2[u], bl2[u+1]);
                        MMA_BF16(oacc[nt], al, bh2[u], bh2[u+1]);
                    }
                }
                // second pair of ntiles needs n-offset +16: separate loads
                uint32_t bh3[4], bl3[4];
                LDSM_X4T(bh3, swadr(sb + SM_VHI, kc*16 + bv_row, bv_c16 + 2));
                LDSM_X4T(bl3, swadr(sb + SM_VLO, kc*16 + bv_row, bv_c16 + 2));
                #pragma unroll
                for (int nt = 2; nt < 4; nt++) {
                    int u = (nt & 1)*2;
                    MMA_BF16(oacc[nt], ah, bh3[u], bh3[u+1]);
                    MMA_BF16(oacc[nt], ah, bl3[u], bl3[u+1]);
                    MMA_BF16(oacc[nt], al, bh3[u], bh3[u+1]);
                }
            }

            // ---- series store + row-sum, prior, sigma ----
            #pragma unroll
            for (int p = 0; p < 4; p++) {
                int rloc = srow + p*16;
                int irow = i0 + rloc;
                size_t off = ((size_t)bh*L_ + irow)*L_ + j0 + sc0;
                float4 s4 = *(const float4*)(Ps + rloc*PSTR + sc0);
                *(float4*)(outS + off) = s4;
                float part = s4.x + s4.y + s4.z + s4.w;
                #pragma unroll
                for (int o = 1; o < 16; o <<= 1) part += __shfl_xor_sync(0xffffffffu, part, o);
                lsum[p] += part;
                float vals[4];
                #pragma unroll
                for (int c = 0; c < 4; c++) {
                    int d = irow - (j0 + sc0 + c);
                    float arg = -(float)(d*d) * i2s24[p];
                    vals[c] = (arg > -87.f) ? (coef4[p] * __expf(arg)) : 0.f;
                }
                *(float4*)(outP + off) = make_float4(vals[0],vals[1],vals[2],vals[3]);
                *(float4*)(outG + off) = make_float4(sig4[p],sig4[p],sig4[p],sig4[p]);
            }
            __syncthreads();
        }

        // ---- publish rl ----
        if ((tx & 15) == 0) {
            #pragma unroll
            for (int p = 0; p < 4; p++) {
                int rloc = srow + p*16;
                float rl = 1.f / lsum[p];
                rlbuf[rloc] = rl;
                g_rl[bh*L_ + i0 + rloc] = rl;
            }
        }
        __syncthreads();

        // ---- V output from O fragments ----
        {
            const int r0 = wm*16 + (lid >> 2);
            const int r1 = r0 + 8;
            const float rl0 = rlbuf[r0], rl1 = rlbuf[r1];
            float* v0 = outV + (((size_t)(b*L_) + i0 + r0)*H_ + h)*D_;
            float* v1 = outV + (((size_t)(b*L_) + i0 + r1)*H_ + h)*D_;
            const int cb = wn*32 + (lid & 3)*2;
            #pragma unroll
            for (int nt = 0; nt < 4; nt++) {
                int col = cb + nt*8;
                *(float2*)(v0 + col) = make_float2(oacc[nt][0]*rl0, oacc[nt][1]*rl0);
                *(float2*)(v1 + col) = make_float2(oacc[nt][2]*rl1, oacc[nt][3]*rl1);
            }
        }

        // ---- non-causal region: zero series + prior + sigma ----
        {
            float4 z = make_float4(0.f,0.f,0.f,0.f);
            #pragma unroll
            for (int p = 0; p < 4; p++) {
                int irow = i0 + srow + p*16;
                #pragma unroll 1
                for (int jt = jlim; jt < NTILE; jt++) {
                    int j0 = jt*64;
                    size_t off = ((size_t)bh*L_ + irow)*L_ + j0 + sc0;
                    float vals[4];
                    #pragma unroll
                    for (int c = 0; c < 4; c++) {
                        int d = irow - (j0 + sc0 + c);
                        float arg = -(float)(d*d) * i2s24[p];
                        vals[c] = (arg > -87.f) ? (coef4[p] * __expf(arg)) : 0.f;
                    }
                    *(float4*)(outS + off) = z;
                    *(float4*)(outP + off) = make_float4(vals[0],vals[1],vals[2],vals[3]);
                    *(float4*)(outG + off) = make_float4(sig4[p],sig4[p],sig4[p],sig4[p]);
                }
            }
        }
        __syncthreads();
    }
}

// ============ epilogue: normalize lower-triangle series ============
__global__ __launch_bounds__(256)
void norm_series(float* __restrict__ out)
{
    const int i  = blockIdx.x;
    const int bh = blockIdx.y;
    const float rl = g_rl[bh*L_ + i];
    float* row = out + (size_t)B_*L_*H_*D_ + ((size_t)bh*L_ + i)*L_;
    const int ncols = (((i >> 6) + 1) << 6);
    for (int c = threadIdx.x*4; c < ncols; c += 256*4) {
        float4 s4 = *(const float4*)(row + c);
        s4.x *= rl; s4.y *= rl; s4.z *= rl; s4.w *= rl;
        *(float4*)(row + c) = s4;
    }
}

extern "C" void kernel_launch(void* const* d_in, const int* in_sizes, int n_in,
                              void* d_out, int out_size) {
    const float* q  = (const float*)d_in[0];
    const float* k  = (const float*)d_in[1];
    const float* v  = (const float*)d_in[2];
    const float* sg = (const float*)d_in[3];

    sigma_prep<<<(B_*H_*L_ + 255)/256, 256>>>(sg);

    cudaFuncSetAttribute(attn_tc, cudaFuncAttributeMaxDynamicSharedMemorySize, SM_TOTAL);
    dim3 grid(NTILE/2, H_, B_);
    attn_tc<<<grid, 256, SM_TOTAL>>>(q, k, v, (float*)d_out);

    dim3 egrid(L_, B_*H_);
    norm_series<<<egrid, 256>>>((float*)d_out);
}